// round 9
// baseline (speedup 1.0000x reference)
#include <cuda_runtime.h>
#include <cuda_fp16.h>
#include <cstdint>

// Fixed shape: B=8, S=4096, H=1024
#define BDIM 8
#define SDIM 4096
#define HDIM 1024

// GEMM tiling
#define BM 128
#define BN 64
#define BKH 32                  // k-chunk (fp16 elems) per stage
#define KT (HDIM / BKH)         // 32 iterations
#define ROWB 80                 // smem row stride bytes (32 halves + 16B pad)
#define APLANE (BM * ROWB)      // 10240
#define BPLANE (BN * ROWB)      // 5120
#define STAGE_BYTES (2 * APLANE + 2 * BPLANE)   // Ah, Al, Bh, Bl = 30720
#define OFF_AH 0
#define OFF_AL APLANE
#define OFF_BH (2 * APLANE)
#define OFF_BL (2 * APLANE + BPLANE)
#define NSTAGE 3
#define SMEM_DYN (NSTAGE * STAGE_BYTES + 512)   // 92672 -> 2 CTAs/SM

// ---------------- device scratch (no allocations allowed) ----------------
__device__ int g_tokpos[BDIM * SDIM];
__device__ int g_slot[BDIM * SDIM];                 // pos -> compacted slot (-1 if dropped)
__device__ int g_nkeep[BDIM];
__device__ int g_nzero[BDIM];
__device__ unsigned g_score[BDIM * SDIM];           // monotone-mapped row max
__device__ __half g_Ahi[BDIM * SDIM * HDIM];        // compacted kept rows, hi
__device__ __half g_Alo[BDIM * SDIM * HDIM];        // compacted kept rows, lo
__device__ __half g_Bhi[HDIM * HDIM];               // W^T [n][k], hi
__device__ __half g_Blo[HDIM * HDIM];               // W^T [n][k], lo

// ---------------- asm helpers (sm_103-base-safe only) ----------------
__device__ __forceinline__ uint32_t smem_u32(const void* p) {
    uint32_t a;
    asm("{ .reg .u64 t; cvta.to.shared.u64 t, %1; cvt.u32.u64 %0, t; }" : "=r"(a) : "l"(p));
    return a;
}
#define CP16(d, s) asm volatile("cp.async.cg.shared.global [%0], [%1], 16;" :: "r"(d), "l"(s))
#define CP_COMMIT() asm volatile("cp.async.commit_group;" ::: "memory")
#define CP_WAIT1() asm volatile("cp.async.wait_group 1;" ::: "memory")

#define LDX4(R, addr) \
    asm volatile("ldmatrix.sync.aligned.m8n8.x4.shared.b16 {%0,%1,%2,%3}, [%4];" \
        : "=r"((R)[0]), "=r"((R)[1]), "=r"((R)[2]), "=r"((R)[3]) : "r"(addr))

#define MMA16816(C, A, B0, B1) \
    asm volatile("mma.sync.aligned.m16n8k16.row.col.f32.f16.f16.f32 " \
        "{%0,%1,%2,%3}, {%4,%5,%6,%7}, {%8,%9}, {%0,%1,%2,%3};" \
        : "+f"((C)[0]), "+f"((C)[1]), "+f"((C)[2]), "+f"((C)[3]) \
        : "r"((A)[0]), "r"((A)[1]), "r"((A)[2]), "r"((A)[3]), "r"(B0), "r"(B1))

__device__ __forceinline__ unsigned mono(float s) {
    unsigned u = __float_as_uint(s);
    return (u & 0x80000000u) ? ~u : (u | 0x80000000u);
}

// ---------------------------------------------------------------------------
// K1: per-row compaction + counts + score reset + inverse slot map
// ---------------------------------------------------------------------------
__global__ void compact_kernel(const float* __restrict__ pmask,
                               const float* __restrict__ amask) {
    int b = blockIdx.x;
    int t = threadIdx.x;
    __shared__ int cnt[1024];
    __shared__ int cntz_s[1024];
    int base = b * SDIM;

    int flags = 0, local = 0, localz = 0;
#pragma unroll
    for (int r = 0; r < 4; r++) {
        int p = t * 4 + r;
        bool k = pmask[base + p] > 0.5f;
        flags |= (int)k << r;
        local += k;
        if (k && amask[base + p] == 0.0f) localz++;
        g_score[base + p] = 0u;
        g_slot[base + p] = -1;
    }
    cnt[t] = local;
    cntz_s[t] = localz;
    __syncthreads();
    for (int off = 1; off < 1024; off <<= 1) {
        int v = (t >= off) ? cnt[t - off] : 0;
        int vz = (t >= off) ? cntz_s[t - off] : 0;
        __syncthreads();
        cnt[t] += v;
        cntz_s[t] += vz;
        __syncthreads();
    }
    int offset = cnt[t] - local;
#pragma unroll
    for (int r = 0; r < 4; r++) {
        if ((flags >> r) & 1) {
            g_tokpos[base + offset] = t * 4 + r;
            g_slot[base + t * 4 + r] = offset;
            offset++;
        }
    }
    if (t == 1023) {
        g_nkeep[b] = cnt[1023];
        g_nzero[b] = cntz_s[1023];
    }
}

// ---------------------------------------------------------------------------
// K_prepW: W[k][n] fp32 -> W^T[n][k] fp16 hi/lo (tiled transpose)
// ---------------------------------------------------------------------------
__global__ void prep_w(const float* __restrict__ W) {
    __shared__ float t[32][33];
    int n0 = blockIdx.x * 32, k0 = blockIdx.y * 32;
    int tx = threadIdx.x, ty = threadIdx.y;
#pragma unroll
    for (int r = 0; r < 4; r++)
        t[ty + r * 8][tx] = W[(size_t)(k0 + ty + r * 8) * HDIM + n0 + tx];
    __syncthreads();
#pragma unroll
    for (int r = 0; r < 4; r++) {
        int n = ty + r * 8;
        float x = t[tx][n];
        __half h = __float2half_rn(x);
        __half l = __float2half_rn(x - __half2float(h));
        size_t d = (size_t)(n0 + n) * HDIM + k0 + tx;
        g_Bhi[d] = h;
        g_Blo[d] = l;
    }
}

// ---------------------------------------------------------------------------
// K_prep_copy: single pass over hidden — copy to out_ret, and for kept rows
// also split fp32 -> fp16 hi/lo into compacted planes. grid 32768, block 128.
// ---------------------------------------------------------------------------
__global__ void prep_copy(const float4* __restrict__ hid, float4* __restrict__ out_ret) {
    int row = blockIdx.x;                       // b*SDIM + s
    const float4* src = hid + (size_t)row * (HDIM / 4);
    float4* dst = out_ret + (size_t)row * (HDIM / 4);
    int slot = g_slot[row];

    if (slot < 0) {
#pragma unroll
        for (int i = 0; i < 2; i++) {
            int e4 = threadIdx.x + i * 128;
            dst[e4] = src[e4];
        }
        return;
    }
    int b = row >> 12;
    size_t dbase = (size_t)((b << 12) + slot) * HDIM;
#pragma unroll
    for (int i = 0; i < 2; i++) {
        int e4 = threadIdx.x + i * 128;
        float4 v = src[e4];
        dst[e4] = v;
        float f[4] = {v.x, v.y, v.z, v.w};
        __half h[4], l[4];
#pragma unroll
        for (int q = 0; q < 4; q++) {
            h[q] = __float2half_rn(f[q]);
            l[q] = __float2half_rn(f[q] - __half2float(h[q]));
        }
        uint2 uh, ul;
        uh.x = ((unsigned)__half_as_ushort(h[1]) << 16) | __half_as_ushort(h[0]);
        uh.y = ((unsigned)__half_as_ushort(h[3]) << 16) | __half_as_ushort(h[2]);
        ul.x = ((unsigned)__half_as_ushort(l[1]) << 16) | __half_as_ushort(l[0]);
        ul.y = ((unsigned)__half_as_ushort(l[3]) << 16) | __half_as_ushort(l[2]);
        *(uint2*)(g_Ahi + dbase + e4 * 4) = uh;
        *(uint2*)(g_Alo + dbase + e4 * 4) = ul;
    }
}

// ---------------------------------------------------------------------------
// K2: exact 3-pass split-fp16 GEMM (ah·bh + al·bh + ah·bl), row-max epilogue
// grid (32, 16, BDIM), block 256 (8 warps, 4x2, warp tile 32x32)
// 3-stage cp.async pipeline (30KB/stage), ONE barrier per k-iter, 2 CTAs/SM
// ---------------------------------------------------------------------------
__global__ void __launch_bounds__(256, 2)
score_gemm(const float* __restrict__ bias) {
    int b = blockIdx.z;
    int nk = g_nkeep[b];
    int m0 = blockIdx.x * BM;
    if (m0 >= nk) return;
    int n0 = blockIdx.y * BN;

    extern __shared__ __align__(128) char sm[];
    uint32_t sb = smem_u32(sm);
    float* biasS = (float*)(sm + NSTAGE * STAGE_BYTES);

    int tid = threadIdx.x, wid = tid >> 5, lane = tid & 31;
    if (tid < BN) biasS[tid] = bias[n0 + tid];

    const __half* gah = g_Ahi + (size_t)(b * SDIM + m0) * HDIM;
    const __half* gal = g_Alo + (size_t)(b * SDIM + m0) * HDIM;
    const __half* gbh = g_Bhi + (size_t)n0 * HDIM;
    const __half* gbl = g_Blo + (size_t)n0 * HDIM;

    // A: 128 rows x 4 chunks = 512 chunks/plane ; B: 64 rows x 4 = 256 chunks/plane
#define LOAD_STAGE(s, k0)                                                     \
    do {                                                                      \
        uint32_t st_ = sb + (s) * STAGE_BYTES;                                \
        _Pragma("unroll")                                                     \
        for (int i_ = 0; i_ < 2; i_++) {                                      \
            int cid_ = tid + i_ * 256;                                        \
            int r_ = cid_ >> 2, c_ = cid_ & 3;                                \
            uint32_t so_ = (uint32_t)(r_ * ROWB + c_ * 16);                   \
            size_t go_ = (size_t)r_ * HDIM + (k0) + c_ * 8;                   \
            CP16(st_ + OFF_AH + so_, gah + go_);                              \
            CP16(st_ + OFF_AL + so_, gal + go_);                              \
        }                                                                     \
        {                                                                     \
            int r_ = tid >> 2, c_ = tid & 3;                                  \
            uint32_t so_ = (uint32_t)(r_ * ROWB + c_ * 16);                   \
            size_t go_ = (size_t)r_ * HDIM + (k0) + c_ * 8;                   \
            CP16(st_ + OFF_BH + so_, gbh + go_);                              \
            CP16(st_ + OFF_BL + so_, gbl + go_);                              \
        }                                                                     \
    } while (0)

    LOAD_STAGE(0, 0);
    CP_COMMIT();
    LOAD_STAGE(1, BKH);
    CP_COMMIT();

    int wm = wid >> 1, wn = wid & 1;      // 4 x 2 warp grid, warp tile 32x32
    float acc[2][4][4];
#pragma unroll
    for (int mt = 0; mt < 2; mt++)
#pragma unroll
        for (int nt = 0; nt < 4; nt++)
#pragma unroll
            for (int e = 0; e < 4; e++) acc[mt][nt][e] = 0.0f;

    uint32_t arow = (uint32_t)(wm * 32 + (lane & 15));
    uint32_t brow = (uint32_t)(wn * 32 + (lane & 15));
    uint32_t kcol = (uint32_t)((lane >> 4) * 16);

    int stage = 0;
    for (int kt = 0; kt < KT; kt++) {
        CP_WAIT1();
        __syncthreads();                 // single barrier per iteration

        // prefetch kt+2 into the buffer consumed at iter kt-1
        if (kt + 2 < KT) {
            int ns = stage + 2;
            if (ns >= NSTAGE) ns -= NSTAGE;
            LOAD_STAGE(ns, (kt + 2) * BKH);
        }
        CP_COMMIT();

        uint32_t st = sb + stage * STAGE_BYTES;
#pragma unroll
        for (int ks = 0; ks < 2; ks++) {
            uint32_t koff = (uint32_t)(ks * 32) + kcol;
            uint32_t bh[2][4], bl[2][4];
#pragma unroll
            for (int g = 0; g < 2; g++) {
                uint32_t rb = st + OFF_BH + (brow + g * 16) * ROWB + koff;
                LDX4(bh[g], rb);
                LDX4(bl[g], rb + BPLANE);
            }
#pragma unroll
            for (int mt = 0; mt < 2; mt++) {
                uint32_t ah[4], al[4];
                uint32_t ra = st + OFF_AH + (arow + mt * 16) * ROWB + koff;
                LDX4(ah, ra);
                LDX4(al, ra + APLANE);
#pragma unroll
                for (int nt = 0; nt < 4; nt++) {
                    int g = nt >> 1, s2 = nt & 1;
                    MMA16816(acc[mt][nt], ah, bh[g][s2], bh[g][s2 + 2]);
                    MMA16816(acc[mt][nt], al, bh[g][s2], bh[g][s2 + 2]);
                    MMA16816(acc[mt][nt], ah, bl[g][s2], bl[g][s2 + 2]);
                }
            }
        }
        stage++;
        if (stage >= NSTAGE) stage = 0;
    }

    // ---- epilogue: bias add + row max + lane reduce + atomicMax ----
    float rmax[2][2];
#pragma unroll
    for (int mt = 0; mt < 2; mt++) { rmax[mt][0] = -3.4e38f; rmax[mt][1] = -3.4e38f; }
#pragma unroll
    for (int mt = 0; mt < 2; mt++)
#pragma unroll
        for (int nt = 0; nt < 4; nt++) {
            int cb = wn * 32 + nt * 8 + (lane & 3) * 2;
            float b0 = biasS[cb], b1 = biasS[cb + 1];
            rmax[mt][0] = fmaxf(rmax[mt][0], fmaxf(acc[mt][nt][0] + b0, acc[mt][nt][1] + b1));
            rmax[mt][1] = fmaxf(rmax[mt][1], fmaxf(acc[mt][nt][2] + b0, acc[mt][nt][3] + b1));
        }
#pragma unroll
    for (int off = 1; off <= 2; off <<= 1)
#pragma unroll
        for (int mt = 0; mt < 2; mt++) {
            rmax[mt][0] = fmaxf(rmax[mt][0], __shfl_xor_sync(0xFFFFFFFFu, rmax[mt][0], off));
            rmax[mt][1] = fmaxf(rmax[mt][1], __shfl_xor_sync(0xFFFFFFFFu, rmax[mt][1], off));
        }
    if ((lane & 3) == 0) {
#pragma unroll
        for (int mt = 0; mt < 2; mt++)
#pragma unroll
            for (int h2 = 0; h2 < 2; h2++) {
                int m = m0 + wm * 32 + mt * 16 + (lane >> 2) + h2 * 8;
                if (m < nk) {
                    int pos = g_tokpos[b * SDIM + m];
                    atomicMax(&g_score[b * SDIM + pos], mono(rmax[mt][h2]));
                }
            }
    }
#undef LOAD_STAGE
}

// ---------------------------------------------------------------------------
// K3: per-row top-T via bitonic sort of rebuilt keys -> new_mask
// ---------------------------------------------------------------------------
__device__ __forceinline__ unsigned long long make_key(int base, int i,
                                                       const float* pmask,
                                                       const float* amask) {
    if (pmask[base + i] <= 0.5f) return 0ull;
    unsigned u = g_score[base + i];
    unsigned bits = (u & 0x80000000u) ? (u & 0x7FFFFFFFu) : ~u;   // un-map
    float sc = __uint_as_float(bits);
    float a = amask[base + i];
    sc = sc + a * 100.0f + a;
    unsigned v = __float_as_uint(sc);
    v = (v & 0x80000000u) ? ~v : (v | 0x80000000u);               // re-map
    return ((unsigned long long)v << 32) | (unsigned long long)(0xFFFFFFFFu - (unsigned)i);
}

__global__ void select_kernel(const float* __restrict__ pmask,
                              const float* __restrict__ amask,
                              float* __restrict__ outmask) {
    int b = blockIdx.x;
    int t = threadIdx.x;
    __shared__ unsigned long long s[SDIM];
    int base = b * SDIM;

    for (int i = t; i < SDIM; i += 1024) s[i] = make_key(base, i, pmask, amask);
    __syncthreads();

    for (int k = 2; k <= SDIM; k <<= 1) {
        for (int j = k >> 1; j > 0; j >>= 1) {
            for (int i = t; i < SDIM; i += 1024) {
                int ixj = i ^ j;
                if (ixj > i) {
                    unsigned long long A = s[i], B = s[ixj];
                    bool up = ((i & k) == 0);
                    if ((A > B) == up) { s[i] = B; s[ixj] = A; }
                }
            }
            __syncthreads();
        }
    }

    int cz = g_nzero[b];
    int T = (int)((float)cz * 0.8f);
    if (T < 1) T = 1;
    unsigned long long thresh = s[SDIM - T];

    for (int i = t; i < SDIM; i += 1024)
        outmask[base + i] = (make_key(base, i, pmask, amask) >= thresh) ? 1.0f : 0.0f;
}

// ---------------------------------------------------------------------------
extern "C" void kernel_launch(void* const* d_in, const int* in_sizes, int n_in,
                              void* d_out, int out_size) {
    const float* hidden = (const float*)d_in[0];
    const float* amask  = (const float*)d_in[1];
    const float* pmask  = (const float*)d_in[2];
    const float* W      = (const float*)d_in[3];
    const float* bias   = (const float*)d_in[4];
    float* out = (float*)d_out;

    const int nh = BDIM * SDIM * HDIM;
    float* out_ret  = out;
    float* out_mask = out + nh;

    cudaFuncSetAttribute(score_gemm, cudaFuncAttributeMaxDynamicSharedMemorySize, SMEM_DYN);

    // compaction + counts + score/slot reset
    compact_kernel<<<BDIM, 1024>>>(pmask, amask);

    // W -> [n][k] fp16 hi/lo
    prep_w<<<dim3(32, 32), dim3(32, 8)>>>(W);

    // single pass: copy hidden -> out_ret, split kept rows into planes
    prep_copy<<<BDIM * SDIM, 128>>>((const float4*)hidden, (float4*)out_ret);

    // exact 3-pass split-fp16 tensor-core score GEMM
    score_gemm<<<dim3(SDIM / BM, HDIM / BN, BDIM), 256, SMEM_DYN>>>(bias);

    // top-T selection per row
    select_kernel<<<BDIM, 1024>>>(pmask, amask, out_mask);
}